// round 6
// baseline (speedup 1.0000x reference)
#include <cuda_runtime.h>
#include <cstdint>
#include <math.h>

#define K_DIM 1024
#define N_EXPERTS 64
#define BM 128
#define KCHUNK 32
#define NLOCAL 16                        // chunks per group (32 total / 2 groups)
#define XS_STRIDE 36                     // 32 + 4 pad
#define XS_FLOATS (128 * XS_STRIDE)
#define WS_FLOATS (64 * XS_STRIDE)
#define STAGE_FLOATS (XS_FLOATS + WS_FLOATS)     // 6912
#define GROUP_FLOATS (2 * STAGE_FLOATS)          // 2 stages
#define SMEM_BYTES (2 * GROUP_FLOATS * 4)        // 110592
#define TH 7e-3f
#define FULL 0xffffffffu

static __device__ __forceinline__ uint32_t smem_u32(const void* p) {
    return (uint32_t)__cvta_generic_to_shared(p);
}
static __device__ __forceinline__ void cp16(uint32_t dst, const void* src) {
    asm volatile("cp.async.cg.shared.global [%0], [%1], 16;" :: "r"(dst), "l"(src) : "memory");
}
#define CP_COMMIT() asm volatile("cp.async.commit_group;" ::: "memory")
#define CP_WAIT1()  asm volatile("cp.async.wait_group 1;" ::: "memory")
#define GBAR(id)    asm volatile("bar.sync %0, 128;" :: "r"(id) : "memory")

#define MMA_TF32(d, a, b) \
    asm volatile("mma.sync.aligned.m16n8k8.row.col.f32.tf32.tf32.f32 " \
        "{%0,%1,%2,%3}, {%4,%5,%6,%7}, {%8,%9}, {%0,%1,%2,%3};" \
        : "+f"((d)[0]), "+f"((d)[1]), "+f"((d)[2]), "+f"((d)[3]) \
        : "r"((a)[0]), "r"((a)[1]), "r"((a)[2]), "r"((a)[3]), "r"((b)[0]), "r"((b)[1]))

#define INS4(vv, ii) do {                                                     \
    const float _v = (vv); const int _i = (ii);                               \
    if (_v > t3) {                                                            \
        if (_v > t2) { t3 = t2; j3 = j2;                                      \
            if (_v > t1) { t2 = t1; j2 = j1;                                  \
                if (_v > t0) { t1 = t0; j1 = j0; t0 = _v; j0 = _i; }          \
                else         { t1 = _v; j1 = _i; } }                          \
            else { t2 = _v; j2 = _i; } }                                      \
        else { t3 = _v; j3 = _i; } }                                          \
} while (0)

__global__ __launch_bounds__(256, 2)
void router_mma_kernel(const float* __restrict__ x,
                       const float* __restrict__ Wm,
                       const float* __restrict__ bias,
                       float* __restrict__ out,
                       int num_tokens) {
    extern __shared__ float smem[];
    const int tid  = threadIdx.x;
    const int gid  = tid >> 7;          // group 0 / 1 (k-split halves)
    const int gtid = tid & 127;
    const int gwid = gtid >> 5;         // warp within group, 0..3
    const int lid  = tid & 31;
    const int bm   = blockIdx.x * BM;

    float* gsmem = smem + gid * GROUP_FLOATS;
    const int g4 = gtid & 7;
    const int rb = gtid >> 3;

    // chunk issue for this group: local chunk n -> global chunk 2n+gid
    auto issue_chunk = [&](int n) {
        const int koff = (2 * n + gid) * KCHUNK;
        const uint32_t base = smem_u32(gsmem + (n & 1) * STAGE_FLOATS);
        const float* gx = x + (size_t)(bm + rb) * K_DIM + koff + g4 * 4;
        #pragma unroll
        for (int i = 0; i < 8; ++i)
            cp16(base + ((rb + 16 * i) * XS_STRIDE + g4 * 4) * 4,
                 gx + (size_t)(16 * i) * K_DIM);
        const uint32_t wbase = base + XS_FLOATS * 4;
        const float* gw = Wm + (size_t)rb * K_DIM + koff + g4 * 4;
        #pragma unroll
        for (int i = 0; i < 4; ++i)
            cp16(wbase + ((rb + 16 * i) * XS_STRIDE + g4 * 4) * 4,
                 gw + (size_t)(16 * i) * K_DIM);
    };

    float acc[4][4][4];
    #pragma unroll
    for (int mt = 0; mt < 4; ++mt)
        #pragma unroll
        for (int nt = 0; nt < 4; ++nt)
            #pragma unroll
            for (int q = 0; q < 4; ++q) acc[mt][nt][q] = 0.0f;

    const int r  = lid >> 2;
    const int cq = lid & 3;
    const int barid = 1 + gid;

    issue_chunk(0); CP_COMMIT();

    #pragma unroll 1
    for (int c = 0; c < NLOCAL; ++c) {
        if (c + 1 < NLOCAL) issue_chunk(c + 1);
        CP_COMMIT();
        CP_WAIT1();
        GBAR(barid);

        const uint32_t* xsp = (const uint32_t*)(gsmem + (c & 1) * STAGE_FLOATS);
        const uint32_t* wsp = xsp + XS_FLOATS;

        #pragma unroll
        for (int ks = 0; ks < 4; ++ks) {
            const int kc = ks * 8 + cq;
            uint32_t bf[4][2], af[4][4];
            #pragma unroll
            for (int nt = 0; nt < 4; ++nt) {
                const int tr = gwid * 32 + nt * 8 + r;
                bf[nt][0] = xsp[tr * XS_STRIDE + kc];
                bf[nt][1] = xsp[tr * XS_STRIDE + kc + 4];
            }
            #pragma unroll
            for (int mt = 0; mt < 4; ++mt) {
                const int er = mt * 16 + r;
                af[mt][0] = wsp[er * XS_STRIDE + kc];
                af[mt][1] = wsp[(er + 8) * XS_STRIDE + kc];
                af[mt][2] = wsp[er * XS_STRIDE + kc + 4];
                af[mt][3] = wsp[(er + 8) * XS_STRIDE + kc + 4];
            }
            #pragma unroll
            for (int mt = 0; mt < 4; ++mt)
                #pragma unroll
                for (int nt = 0; nt < 4; ++nt)
                    MMA_TF32(acc[mt][nt], af[mt], bf[nt]);
        }
        GBAR(barid);
    }

    // ---- merge k-split partials: group 1 -> smem, group 0 adds ----
    __syncthreads();
    if (gid == 1) {
        float* red = smem + GROUP_FLOATS;   // group 1's own region
        #pragma unroll
        for (int mt = 0; mt < 4; ++mt)
            #pragma unroll
            for (int nt = 0; nt < 4; ++nt)
                #pragma unroll
                for (int q = 0; q < 4; ++q)
                    red[(size_t)gtid * 64 + (mt * 4 + nt) * 4 + q] = acc[mt][nt][q];
    }
    __syncthreads();
    if (gid == 0) {
        const float* red = smem + GROUP_FLOATS;
        #pragma unroll
        for (int mt = 0; mt < 4; ++mt)
            #pragma unroll
            for (int nt = 0; nt < 4; ++nt)
                #pragma unroll
                for (int q = 0; q < 4; ++q)
                    acc[mt][nt][q] += red[(size_t)gtid * 64 + (mt * 4 + nt) * 4 + q];
    }

    if (gid != 0) return;

    // ---------------- epilogue (group 0 only, 4 warps x 32 tokens) ----------------
    float bl[8];
    #pragma unroll
    for (int j = 0; j < 8; ++j)
        bl[j] = __ldg(bias + (j & 3) * 16 + r + (j >> 2) * 8);

    float* oid = out + (size_t)num_tokens * 2;

    #pragma unroll 1
    for (int nt = 0; nt < 4; ++nt) {
        #pragma unroll 1
        for (int p = 0; p < 2; ++p) {
            float v[8];
            #pragma unroll
            for (int j = 0; j < 8; ++j)
                v[j] = acc[j & 3][nt][(j >> 2) * 2 + p] + bl[j];

            float t0 = -INFINITY, t1 = -INFINITY, t2 = -INFINITY, t3 = -INFINITY;
            int j0 = 0, j1 = 0, j2 = 0, j3 = 0;
            #pragma unroll
            for (int j = 0; j < 8; ++j)
                INS4(v[j], (j & 3) * 16 + r + (j >> 2) * 8);

            #pragma unroll
            for (int d = 4; d < 32; d <<= 1) {
                const float o0 = __shfl_xor_sync(FULL, t0, d);
                const float o1 = __shfl_xor_sync(FULL, t1, d);
                const float o2 = __shfl_xor_sync(FULL, t2, d);
                const float o3 = __shfl_xor_sync(FULL, t3, d);
                const int   q0 = __shfl_xor_sync(FULL, j0, d);
                const int   q1 = __shfl_xor_sync(FULL, j1, d);
                const int   q2 = __shfl_xor_sync(FULL, j2, d);
                const int   q3 = __shfl_xor_sync(FULL, j3, d);
                INS4(o0, q0); INS4(o1, q1); INS4(o2, q2); INS4(o3, q3);
            }

            float s = 0.0f;
            #pragma unroll
            for (int j = 0; j < 8; ++j) s += __expf(v[j] - t0);
            #pragma unroll
            for (int d = 4; d < 32; d <<= 1) s += __shfl_xor_sync(FULL, s, d);

            float g1 = 1.0f / s, g2 = __expf(t1 - t0) / s;
            int i1 = j0, i2 = j1;

            const bool flag = (t0 - t1 < TH) || (t1 - t2 < TH);
            const bool deep = (t1 - t3 < TH);
            unsigned fb = __ballot_sync(FULL, flag) & 0xFu;
            const unsigned db = __ballot_sync(FULL, deep) & 0xFu;

            while (fb) {
                const int c4 = __ffs(fb) - 1; fb &= fb - 1;
                const int tk = bm + gwid * 32 + nt * 8 + 2 * c4 + p;
                const float* xr = x + (size_t)tk * K_DIM;
                float em1, em2, ns; int ei1, ei2;

                if ((db >> c4) & 1) {
                    const int e0 = lid * 2, e1 = e0 + 1;
                    const float* w0 = Wm + (size_t)e0 * K_DIM;
                    const float* w1 = Wm + (size_t)e1 * K_DIM;
                    float a0 = 0.f, a1 = 0.f;
                    #pragma unroll 2
                    for (int k = 0; k < K_DIM; k += 4) {
                        const float4 xv = *(const float4*)(xr + k);
                        const float4 v0 = *(const float4*)(w0 + k);
                        const float4 v1 = *(const float4*)(w1 + k);
                        a0 = fmaf(xv.x, v0.x, a0); a0 = fmaf(xv.y, v0.y, a0);
                        a0 = fmaf(xv.z, v0.z, a0); a0 = fmaf(xv.w, v0.w, a0);
                        a1 = fmaf(xv.x, v1.x, a1); a1 = fmaf(xv.y, v1.y, a1);
                        a1 = fmaf(xv.z, v1.z, a1); a1 = fmaf(xv.w, v1.w, a1);
                    }
                    a0 += __ldg(bias + e0); a1 += __ldg(bias + e1);
                    float fm1, fm2; int fi1, fi2;
                    if (a0 >= a1) { fm1 = a0; fi1 = e0; fm2 = a1; fi2 = e1; }
                    else          { fm1 = a1; fi1 = e1; fm2 = a0; fi2 = e0; }
                    #pragma unroll
                    for (int d = 1; d < 32; d <<= 1) {
                        const float om1 = __shfl_xor_sync(FULL, fm1, d);
                        const float om2 = __shfl_xor_sync(FULL, fm2, d);
                        const int   oi1 = __shfl_xor_sync(FULL, fi1, d);
                        const int   oi2 = __shfl_xor_sync(FULL, fi2, d);
                        if (om1 > fm1) {
                            if (fm1 > om2) { fm2 = fm1; fi2 = fi1; }
                            else           { fm2 = om2; fi2 = oi2; }
                            fm1 = om1; fi1 = oi1;
                        } else if (om1 > fm2) { fm2 = om1; fi2 = oi1; }
                    }
                    float fs = __expf(a0 - fm1) + __expf(a1 - fm1);
                    #pragma unroll
                    for (int d = 1; d < 32; d <<= 1)
                        fs += __shfl_xor_sync(FULL, fs, d);
                    em1 = fm1; ei1 = fi1; em2 = fm2; ei2 = fi2; ns = fs;
                } else {
                    const float qm = __shfl_sync(FULL, t0, c4);
                    const float qs = __shfl_sync(FULL, s, c4);
                    int qi[4];
                    qi[0] = __shfl_sync(FULL, j0, c4);
                    qi[1] = __shfl_sync(FULL, j1, c4);
                    qi[2] = __shfl_sync(FULL, j2, c4);
                    qi[3] = __shfl_sync(FULL, j3, c4);
                    float ds[4] = {0.f, 0.f, 0.f, 0.f};
                    #pragma unroll
                    for (int u = 0; u < 8; ++u) {
                        const int k = u * 128 + lid * 4;
                        const float4 xv = *(const float4*)(xr + k);
                        #pragma unroll
                        for (int q = 0; q < 4; ++q) {
                            const float4 wv = *(const float4*)(Wm + (size_t)qi[q] * K_DIM + k);
                            ds[q] = fmaf(xv.x, wv.x, ds[q]);
                            ds[q] = fmaf(xv.y, wv.y, ds[q]);
                            ds[q] = fmaf(xv.z, wv.z, ds[q]);
                            ds[q] = fmaf(xv.w, wv.w, ds[q]);
                        }
                    }
                    #pragma unroll
                    for (int d = 1; d < 32; d <<= 1) {
                        #pragma unroll
                        for (int q = 0; q < 4; ++q)
                            ds[q] += __shfl_xor_sync(FULL, ds[q], d);
                    }
                    #pragma unroll
                    for (int q = 0; q < 4; ++q) ds[q] += __ldg(bias + qi[q]);
                    em1 = ds[0]; ei1 = qi[0]; em2 = -INFINITY; ei2 = 0;
                    #pragma unroll
                    for (int q = 1; q < 4; ++q) {
                        if (ds[q] > em1) { em2 = em1; ei2 = ei1; em1 = ds[q]; ei1 = qi[q]; }
                        else if (ds[q] > em2) { em2 = ds[q]; ei2 = qi[q]; }
                    }
                    ns = qs * __expf(qm - em1);
                }
                if (cq == c4) {
                    g1 = 1.0f / ns; g2 = __expf(em2 - em1) / ns;
                    i1 = ei1; i2 = ei2;
                }
            }

            if (r == 0) {
                const int tk = bm + gwid * 32 + nt * 8 + 2 * cq + p;
                *(float2*)&out[tk * 2] = make_float2(g1, g2);
                *(float2*)&oid[tk * 2] = make_float2((float)i1, (float)i2);
            }
        }
    }
}

extern "C" void kernel_launch(void* const* d_in, const int* in_sizes, int n_in,
                              void* d_out, int out_size) {
    const float* x = (const float*)d_in[0];   // [8,4096,1024]
    const float* W = (const float*)d_in[1];   // [64,1024]
    const float* b = (const float*)d_in[2];   // [64]
    float* out = (float*)d_out;

    const int num_tokens = in_sizes[0] / K_DIM;   // 32768
    const int grid = num_tokens / BM;             // 256

    cudaFuncSetAttribute(router_mma_kernel,
                         cudaFuncAttributeMaxDynamicSharedMemorySize, SMEM_BYTES);
    router_mma_kernel<<<grid, 256, SMEM_BYTES>>>(x, W, b, out, num_tokens);
}

// round 7
// speedup vs baseline: 1.0129x; 1.0129x over previous
#include <cuda_runtime.h>
#include <cstdint>
#include <math.h>

#define K_DIM 1024
#define N_EXPERTS 64
#define BM 128
#define KCHUNK 32
#define NCHUNK 32
#define XS_STRIDE 36
#define XS_FLOATS (128 * XS_STRIDE)          // 4608
#define WS_FLOATS (64 * XS_STRIDE)           // 2304
#define STAGE_FLOATS (XS_FLOATS + WS_FLOATS) // 6912
#define SMEM_FLOATS (2 * STAGE_FLOATS)       // 13824 -> 55296 B
#define LG_STRIDE 68
#define TH 7e-3f
#define FULL 0xffffffffu

static __device__ __forceinline__ uint32_t smem_u32(const void* p) {
    return (uint32_t)__cvta_generic_to_shared(p);
}
static __device__ __forceinline__ void cp16(uint32_t dst, const void* src) {
    asm volatile("cp.async.cg.shared.global [%0], [%1], 16;" :: "r"(dst), "l"(src) : "memory");
}
#define CP_COMMIT() asm volatile("cp.async.commit_group;" ::: "memory")
#define CP_WAIT1()  asm volatile("cp.async.wait_group 1;" ::: "memory")
#define CP_WAIT0()  asm volatile("cp.async.wait_group 0;" ::: "memory")

#define MMA_TF32(d, a, b) \
    asm volatile("mma.sync.aligned.m16n8k8.row.col.f32.tf32.tf32.f32 " \
        "{%0,%1,%2,%3}, {%4,%5,%6,%7}, {%8,%9}, {%0,%1,%2,%3};" \
        : "+f"((d)[0]), "+f"((d)[1]), "+f"((d)[2]), "+f"((d)[3]) \
        : "r"((a)[0]), "r"((a)[1]), "r"((a)[2]), "r"((a)[3]), "r"((b)[0]), "r"((b)[1]))

#define INS4(vv, ii) do {                                                     \
    const float _v = (vv); const int _i = (ii);                               \
    if (_v > t3) {                                                            \
        if (_v > t2) { t3 = t2; j3 = j2;                                      \
            if (_v > t1) { t2 = t1; j2 = j1;                                  \
                if (_v > t0) { t1 = t0; j1 = j0; t0 = _v; j0 = _i; }          \
                else         { t1 = _v; j1 = _i; } }                          \
            else { t2 = _v; j2 = _i; } }                                      \
        else { t3 = _v; j3 = _i; } }                                          \
} while (0)

__global__ __launch_bounds__(256, 2)
void router_hybrid_kernel(const float* __restrict__ x,
                          const float* __restrict__ Wm,
                          const float* __restrict__ bias,
                          float* __restrict__ out,
                          int num_tokens) {
    extern __shared__ float smem[];
    const int tid = threadIdx.x;
    const int wid = tid >> 5;
    const int lid = tid & 31;
    const int bm  = blockIdx.x * BM;

    // cp.async mapping: 256 threads, 6 granules each
    const int g  = tid & 7;     // 16B granule (k offset g*4)
    const int rb = tid >> 3;    // base row 0..31

    auto issue_chunk = [&](int c) {
        const uint32_t base = smem_u32(smem + (c & 1) * STAGE_FLOATS);
        const int koff = c * KCHUNK;
        const float* gx = x + (size_t)(bm + rb) * K_DIM + koff + g * 4;
        #pragma unroll
        for (int i = 0; i < 4; ++i)
            cp16(base + ((rb + 32 * i) * XS_STRIDE + g * 4) * 4,
                 gx + (size_t)(32 * i) * K_DIM);
        const uint32_t wbase = base + XS_FLOATS * 4;
        const float* gw = Wm + (size_t)rb * K_DIM + koff + g * 4;
        #pragma unroll
        for (int i = 0; i < 2; ++i)
            cp16(wbase + ((rb + 32 * i) * XS_STRIDE + g * 4) * 4,
                 gw + (size_t)(32 * i) * K_DIM);
    };

    // ---- per-group state ----
    // FFMA group (wid 0..3): thread = (tym2 0..31 tokens, txk2 0..3 experts)
    const int txk2 = tid & 3;
    const int tym2 = (tid & 127) >> 2;
    float facc[4][8];
    #pragma unroll
    for (int i = 0; i < 4; ++i)
        #pragma unroll
        for (int j = 0; j < 8; ++j) facc[i][j] = 0.0f;

    // MMA group (wid 4..7)
    const int gwid = wid - 4;
    const int r  = lid >> 2;
    const int cq = lid & 3;
    float acc[2][4][4];
    #pragma unroll
    for (int mt = 0; mt < 2; ++mt)
        #pragma unroll
        for (int nt = 0; nt < 4; ++nt)
            #pragma unroll
            for (int q = 0; q < 4; ++q) acc[mt][nt][q] = 0.0f;

    issue_chunk(0); CP_COMMIT();

    #pragma unroll 1
    for (int c = 0; c < NCHUNK; ++c) {
        if (c + 1 < NCHUNK) issue_chunk(c + 1);
        CP_COMMIT();
        if (c + 1 < NCHUNK) { CP_WAIT1(); } else { CP_WAIT0(); }
        __syncthreads();

        const float* xs = smem + (c & 1) * STAGE_FLOATS;
        const float* ws = xs + XS_FLOATS;

        if (wid < 4) {
            // ---- fp32 FFMA: experts 0..31 ----
            #pragma unroll
            for (int k4 = 0; k4 < 8; ++k4) {
                float4 xv[4];
                #pragma unroll
                for (int i = 0; i < 4; ++i)
                    xv[i] = *(const float4*)&xs[(tym2 + 32 * i) * XS_STRIDE + k4 * 4];
                #pragma unroll
                for (int j = 0; j < 8; ++j) {
                    const float4 wv = *(const float4*)&ws[(txk2 + 4 * j) * XS_STRIDE + k4 * 4];
                    #pragma unroll
                    for (int i = 0; i < 4; ++i) {
                        facc[i][j] = fmaf(xv[i].x, wv.x, facc[i][j]);
                        facc[i][j] = fmaf(xv[i].y, wv.y, facc[i][j]);
                        facc[i][j] = fmaf(xv[i].z, wv.z, facc[i][j]);
                        facc[i][j] = fmaf(xv[i].w, wv.w, facc[i][j]);
                    }
                }
            }
        } else {
            // ---- tf32 MMA: experts 32..63 ----
            const uint32_t* xsp = (const uint32_t*)xs;
            const uint32_t* wsp = (const uint32_t*)ws;
            #pragma unroll
            for (int ks = 0; ks < 4; ++ks) {
                const int kc = ks * 8 + cq;
                uint32_t bf[4][2], af[2][4];
                #pragma unroll
                for (int nt = 0; nt < 4; ++nt) {
                    const int tr = gwid * 32 + nt * 8 + r;
                    bf[nt][0] = xsp[tr * XS_STRIDE + kc];
                    bf[nt][1] = xsp[tr * XS_STRIDE + kc + 4];
                }
                #pragma unroll
                for (int mt = 0; mt < 2; ++mt) {
                    const int er = 32 + mt * 16 + r;
                    af[mt][0] = wsp[er * XS_STRIDE + kc];
                    af[mt][1] = wsp[(er + 8) * XS_STRIDE + kc];
                    af[mt][2] = wsp[er * XS_STRIDE + kc + 4];
                    af[mt][3] = wsp[(er + 8) * XS_STRIDE + kc + 4];
                }
                #pragma unroll
                for (int mt = 0; mt < 2; ++mt)
                    #pragma unroll
                    for (int nt = 0; nt < 4; ++nt)
                        MMA_TF32(acc[mt][nt], af[mt], bf[nt]);
            }
        }
        __syncthreads();
    }

    // ---- dump logits to smem (aliases stage buffers) ----
    float* lg = smem;
    if (wid < 4) {
        #pragma unroll
        for (int i = 0; i < 4; ++i)
            #pragma unroll
            for (int j = 0; j < 8; ++j)
                lg[(tym2 + 32 * i) * LG_STRIDE + txk2 + 4 * j] = facc[i][j];
    } else {
        #pragma unroll
        for (int mt = 0; mt < 2; ++mt)
            #pragma unroll
            for (int nt = 0; nt < 4; ++nt)
                #pragma unroll
                for (int q = 0; q < 4; ++q) {
                    const int e  = 32 + mt * 16 + r + (q >> 1) * 8;
                    const int tk = gwid * 32 + nt * 8 + 2 * cq + (q & 1);
                    lg[tk * LG_STRIDE + e] = acc[mt][nt][q];
                }
    }
    __syncthreads();
    if (wid >= 4) return;

    // ---- per-token epilogue: thread tid owns token bm+tid ----
    const float4* b4 = (const float4*)bias;
    const float4* lrow = (const float4*)&lg[tid * LG_STRIDE];

    float t0 = -INFINITY, t1 = -INFINITY, t2 = -INFINITY, t3 = -INFINITY;
    int j0 = 0, j1 = 0, j2 = 0, j3 = 0;
    #pragma unroll
    for (int i = 0; i < 16; ++i) {
        const float4 lv = lrow[i];
        const float4 bv = __ldg(b4 + i);
        INS4(lv.x + bv.x, i * 4 + 0);
        INS4(lv.y + bv.y, i * 4 + 1);
        INS4(lv.z + bv.z, i * 4 + 2);
        INS4(lv.w + bv.w, i * 4 + 3);
    }
    float s = 0.0f;
    #pragma unroll
    for (int i = 0; i < 16; ++i) {
        const float4 lv = lrow[i];
        const float4 bv = __ldg(b4 + i);
        s += __expf(lv.x + bv.x - t0) + __expf(lv.y + bv.y - t0)
           + __expf(lv.z + bv.z - t0) + __expf(lv.w + bv.w - t0);
    }

    float g1 = 1.0f / s, g2 = __expf(t1 - t0) / s;
    int i1 = j0, i2 = j1;

    const bool flag = (t0 - t1 < TH) || (t1 - t2 < TH);
    const bool deep = (t1 - t3 < TH);
    unsigned fb = __ballot_sync(FULL, flag);
    const unsigned db = __ballot_sync(FULL, deep);

    while (fb) {
        const int b = __ffs(fb) - 1; fb &= fb - 1;
        const int tk = bm + wid * 32 + b;
        const float* xr = x + (size_t)tk * K_DIM;
        float em1, em2, ns; int ei1, ei2;

        if ((db >> b) & 1) {
            // full exact recompute: lane handles experts 2*lid, 2*lid+1
            const int e0 = lid * 2, e1 = e0 + 1;
            const float* w0 = Wm + (size_t)e0 * K_DIM;
            const float* w1 = Wm + (size_t)e1 * K_DIM;
            float a0 = 0.f, a1 = 0.f;
            #pragma unroll 2
            for (int k = 0; k < K_DIM; k += 4) {
                const float4 xv = *(const float4*)(xr + k);
                const float4 v0 = *(const float4*)(w0 + k);
                const float4 v1 = *(const float4*)(w1 + k);
                a0 = fmaf(xv.x, v0.x, a0); a0 = fmaf(xv.y, v0.y, a0);
                a0 = fmaf(xv.z, v0.z, a0); a0 = fmaf(xv.w, v0.w, a0);
                a1 = fmaf(xv.x, v1.x, a1); a1 = fmaf(xv.y, v1.y, a1);
                a1 = fmaf(xv.z, v1.z, a1); a1 = fmaf(xv.w, v1.w, a1);
            }
            a0 += __ldg(bias + e0); a1 += __ldg(bias + e1);
            float fm1, fm2; int fi1, fi2;
            if (a0 >= a1) { fm1 = a0; fi1 = e0; fm2 = a1; fi2 = e1; }
            else          { fm1 = a1; fi1 = e1; fm2 = a0; fi2 = e0; }
            #pragma unroll
            for (int d = 1; d < 32; d <<= 1) {
                const float om1 = __shfl_xor_sync(FULL, fm1, d);
                const float om2 = __shfl_xor_sync(FULL, fm2, d);
                const int   oi1 = __shfl_xor_sync(FULL, fi1, d);
                const int   oi2 = __shfl_xor_sync(FULL, fi2, d);
                if (om1 > fm1) {
                    if (fm1 > om2) { fm2 = fm1; fi2 = fi1; }
                    else           { fm2 = om2; fi2 = oi2; }
                    fm1 = om1; fi1 = oi1;
                } else if (om1 > fm2) { fm2 = om1; fi2 = oi1; }
            }
            float fs = __expf(a0 - fm1) + __expf(a1 - fm1);
            #pragma unroll
            for (int d = 1; d < 32; d <<= 1)
                fs += __shfl_xor_sync(FULL, fs, d);
            em1 = fm1; ei1 = fi1; em2 = fm2; ei2 = fi2; ns = fs;
        } else {
            // candidate path: exact top-4 recompute
            const float qm = __shfl_sync(FULL, t0, b);
            const float qs = __shfl_sync(FULL, s, b);
            int qi[4];
            qi[0] = __shfl_sync(FULL, j0, b);
            qi[1] = __shfl_sync(FULL, j1, b);
            qi[2] = __shfl_sync(FULL, j2, b);
            qi[3] = __shfl_sync(FULL, j3, b);
            float ds[4] = {0.f, 0.f, 0.f, 0.f};
            #pragma unroll
            for (int u = 0; u < 8; ++u) {
                const int k = u * 128 + lid * 4;
                const float4 xv = *(const float4*)(xr + k);
                #pragma unroll
                for (int q = 0; q < 4; ++q) {
                    const float4 wv = *(const float4*)(Wm + (size_t)qi[q] * K_DIM + k);
                    ds[q] = fmaf(xv.x, wv.x, ds[q]);
                    ds[q] = fmaf(xv.y, wv.y, ds[q]);
                    ds[q] = fmaf(xv.z, wv.z, ds[q]);
                    ds[q] = fmaf(xv.w, wv.w, ds[q]);
                }
            }
            #pragma unroll
            for (int d = 1; d < 32; d <<= 1) {
                #pragma unroll
                for (int q = 0; q < 4; ++q)
                    ds[q] += __shfl_xor_sync(FULL, ds[q], d);
            }
            #pragma unroll
            for (int q = 0; q < 4; ++q) ds[q] += __ldg(bias + qi[q]);
            em1 = ds[0]; ei1 = qi[0]; em2 = -INFINITY; ei2 = 0;
            #pragma unroll
            for (int q = 1; q < 4; ++q) {
                if (ds[q] > em1) { em2 = em1; ei2 = ei1; em1 = ds[q]; ei1 = qi[q]; }
                else if (ds[q] > em2) { em2 = ds[q]; ei2 = qi[q]; }
            }
            ns = qs * __expf(qm - em1);
        }
        if (lid == b) {
            g1 = 1.0f / ns; g2 = __expf(em2 - em1) / ns;
            i1 = ei1; i2 = ei2;
        }
    }

    {
        const int tk = bm + tid;
        float* oid = out + (size_t)num_tokens * 2;
        *(float2*)&out[tk * 2] = make_float2(g1, g2);
        *(float2*)&oid[tk * 2] = make_float2((float)i1, (float)i2);
    }
}

extern "C" void kernel_launch(void* const* d_in, const int* in_sizes, int n_in,
                              void* d_out, int out_size) {
    const float* x = (const float*)d_in[0];   // [8,4096,1024]
    const float* W = (const float*)d_in[1];   // [64,1024]
    const float* b = (const float*)d_in[2];   // [64]
    float* out = (float*)d_out;

    const int num_tokens = in_sizes[0] / K_DIM;   // 32768
    const int grid = num_tokens / BM;             // 256

    cudaFuncSetAttribute(router_hybrid_kernel,
                         cudaFuncAttributeMaxDynamicSharedMemorySize, SMEM_FLOATS * 4);
    router_hybrid_kernel<<<grid, 256, SMEM_FLOATS * 4>>>(x, W, b, out, num_tokens);
}

// round 8
// speedup vs baseline: 1.2229x; 1.2073x over previous
#include <cuda_runtime.h>
#include <cstdint>
#include <math.h>

#define K_DIM 1024
#define N_EXPERTS 64
#define BM 128
#define KCHUNK 32
#define NCHUNK 32
#define XS_STRIDE 36
#define XS_FLOATS (128 * XS_STRIDE)
#define WS_FLOATS (64 * XS_STRIDE)
#define STAGE_FLOATS (XS_FLOATS + WS_FLOATS)   // 6912 floats
#define SMEM_BYTES (2 * STAGE_FLOATS * 4)      // 55296
#define LG_STRIDE 68
#define TH 7e-3f
#define FULL 0xffffffffu

#define MMA_TF32(d, a, b) \
    asm volatile("mma.sync.aligned.m16n8k8.row.col.f32.tf32.tf32.f32 " \
        "{%0,%1,%2,%3}, {%4,%5,%6,%7}, {%8,%9}, {%0,%1,%2,%3};" \
        : "+f"((d)[0]), "+f"((d)[1]), "+f"((d)[2]), "+f"((d)[3]) \
        : "r"((a)[0]), "r"((a)[1]), "r"((a)[2]), "r"((a)[3]), "r"((b)[0]), "r"((b)[1]))

#define INS4(vv, ii) do {                                                     \
    const float _v = (vv); const int _i = (ii);                               \
    if (_v > t3) {                                                            \
        if (_v > t2) { t3 = t2; j3 = j2;                                      \
            if (_v > t1) { t2 = t1; j2 = j1;                                  \
                if (_v > t0) { t1 = t0; j1 = j0; t0 = _v; j0 = _i; }          \
                else         { t1 = _v; j1 = _i; } }                          \
            else { t2 = _v; j2 = _i; } }                                      \
        else { t3 = _v; j3 = _i; } }                                          \
} while (0)

__global__ __launch_bounds__(256, 2)
void router_mma2_kernel(const float* __restrict__ x,
                        const float* __restrict__ Wm,
                        const float* __restrict__ bias,
                        float* __restrict__ out,
                        int num_tokens) {
    extern __shared__ float smem[];
    const int tid = threadIdx.x;
    const int wid = tid >> 5;
    const int lid = tid & 31;
    const int bm  = blockIdx.x * BM;

    // loader mapping: 256 threads x 6 float4 each per chunk
    const int g  = tid & 7;     // 16B granule (k offset g*4 within chunk)
    const int rb = tid >> 3;    // base row 0..31

    float4 xv[4], wv[2];
    auto ldg_chunk = [&](int c) {
        const float* gx = x + (size_t)(bm + rb) * K_DIM + c * KCHUNK + g * 4;
        #pragma unroll
        for (int i = 0; i < 4; ++i)
            xv[i] = __ldg((const float4*)(gx + (size_t)(32 * i) * K_DIM));
        const float* gw = Wm + (size_t)rb * K_DIM + c * KCHUNK + g * 4;
        #pragma unroll
        for (int i = 0; i < 2; ++i)
            wv[i] = __ldg((const float4*)(gw + (size_t)(32 * i) * K_DIM));
    };
    auto sts_chunk = [&](int buf) {
        float* xs = smem + buf * STAGE_FLOATS;
        #pragma unroll
        for (int i = 0; i < 4; ++i)
            *(float4*)&xs[(rb + 32 * i) * XS_STRIDE + g * 4] = xv[i];
        float* ws = xs + XS_FLOATS;
        #pragma unroll
        for (int i = 0; i < 2; ++i)
            *(float4*)&ws[(rb + 32 * i) * XS_STRIDE + g * 4] = wv[i];
    };

    const int r  = lid >> 2;
    const int cq = lid & 3;

    // acc[mt][nt][q]: experts mt*16 + r (+8), tokens wid*16 + nt*8 + 2cq (+1)
    float acc[4][2][4];
    #pragma unroll
    for (int mt = 0; mt < 4; ++mt)
        #pragma unroll
        for (int nt = 0; nt < 2; ++nt)
            #pragma unroll
            for (int q = 0; q < 4; ++q) acc[mt][nt][q] = 0.0f;

    ldg_chunk(0);
    sts_chunk(0);
    __syncthreads();

    #pragma unroll 1
    for (int c = 0; c < NCHUNK; ++c) {
        if (c + 1 < NCHUNK) ldg_chunk(c + 1);

        const uint32_t* xsp = (const uint32_t*)(smem + (c & 1) * STAGE_FLOATS);
        const uint32_t* wsp = xsp + XS_FLOATS;

        #pragma unroll
        for (int ks = 0; ks < 4; ++ks) {
            const int kc = ks * 8 + cq;
            uint32_t bf[2][2], af[4][4];
            #pragma unroll
            for (int nt = 0; nt < 2; ++nt) {
                const int tr = wid * 16 + nt * 8 + r;
                bf[nt][0] = xsp[tr * XS_STRIDE + kc];
                bf[nt][1] = xsp[tr * XS_STRIDE + kc + 4];
            }
            #pragma unroll
            for (int mt = 0; mt < 4; ++mt) {
                const int er = mt * 16 + r;
                af[mt][0] = wsp[er * XS_STRIDE + kc];
                af[mt][1] = wsp[(er + 8) * XS_STRIDE + kc];
                af[mt][2] = wsp[er * XS_STRIDE + kc + 4];
                af[mt][3] = wsp[(er + 8) * XS_STRIDE + kc + 4];
            }
            #pragma unroll
            for (int mt = 0; mt < 4; ++mt)
                #pragma unroll
                for (int nt = 0; nt < 2; ++nt)
                    MMA_TF32(acc[mt][nt], af[mt], bf[nt]);
        }
        __syncthreads();
        if (c + 1 < NCHUNK) {
            sts_chunk((c + 1) & 1);
            __syncthreads();
        }
    }

    // ---- dump logits (no bias) to smem; aliases stage buffers ----
    float* lg = smem;
    #pragma unroll
    for (int mt = 0; mt < 4; ++mt)
        #pragma unroll
        for (int nt = 0; nt < 2; ++nt)
            #pragma unroll
            for (int q = 0; q < 4; ++q) {
                const int tk = wid * 16 + nt * 8 + 2 * cq + (q & 1);
                const int e  = mt * 16 + r + (q >> 1) * 8;
                lg[tk * LG_STRIDE + e] = acc[mt][nt][q];
            }
    __syncthreads();
    if (wid >= 4) return;

    // ---- per-token epilogue: thread tid (<128) owns token bm+tid ----
    const float4* b4 = (const float4*)bias;
    const float4* lrow = (const float4*)&lg[tid * LG_STRIDE];

    float t0 = -INFINITY, t1 = -INFINITY, t2 = -INFINITY, t3 = -INFINITY;
    int j0 = 0, j1 = 0, j2 = 0, j3 = 0;
    #pragma unroll
    for (int i = 0; i < 16; ++i) {
        const float4 lv = lrow[i];
        const float4 bv = __ldg(b4 + i);
        INS4(lv.x + bv.x, i * 4 + 0);
        INS4(lv.y + bv.y, i * 4 + 1);
        INS4(lv.z + bv.z, i * 4 + 2);
        INS4(lv.w + bv.w, i * 4 + 3);
    }
    float s = 0.0f;
    #pragma unroll
    for (int i = 0; i < 16; ++i) {
        const float4 lv = lrow[i];
        const float4 bv = __ldg(b4 + i);
        s += __expf(lv.x + bv.x - t0) + __expf(lv.y + bv.y - t0)
           + __expf(lv.z + bv.z - t0) + __expf(lv.w + bv.w - t0);
    }

    float g1 = 1.0f / s, g2 = __expf(t1 - t0) / s;
    int i1 = j0, i2 = j1;

    const bool flag = (t0 - t1 < TH) || (t1 - t2 < TH);
    const bool deep = (t1 - t3 < TH);
    unsigned fb = __ballot_sync(FULL, flag);
    const unsigned db = __ballot_sync(FULL, deep);

    while (fb) {
        const int b = __ffs(fb) - 1; fb &= fb - 1;
        const int tk = bm + wid * 32 + b;
        const float* xr = x + (size_t)tk * K_DIM;
        float em1, em2, ns; int ei1, ei2;

        if ((db >> b) & 1) {
            // full exact fp32 recompute: lane handles experts 2*lid, 2*lid+1
            const int e0 = lid * 2, e1 = e0 + 1;
            const float* w0 = Wm + (size_t)e0 * K_DIM;
            const float* w1 = Wm + (size_t)e1 * K_DIM;
            float a0 = 0.f, a1 = 0.f;
            #pragma unroll 2
            for (int k = 0; k < K_DIM; k += 4) {
                const float4 xq = *(const float4*)(xr + k);
                const float4 v0 = *(const float4*)(w0 + k);
                const float4 v1 = *(const float4*)(w1 + k);
                a0 = fmaf(xq.x, v0.x, a0); a0 = fmaf(xq.y, v0.y, a0);
                a0 = fmaf(xq.z, v0.z, a0); a0 = fmaf(xq.w, v0.w, a0);
                a1 = fmaf(xq.x, v1.x, a1); a1 = fmaf(xq.y, v1.y, a1);
                a1 = fmaf(xq.z, v1.z, a1); a1 = fmaf(xq.w, v1.w, a1);
            }
            a0 += __ldg(bias + e0); a1 += __ldg(bias + e1);
            float fm1, fm2; int fi1, fi2;
            if (a0 >= a1) { fm1 = a0; fi1 = e0; fm2 = a1; fi2 = e1; }
            else          { fm1 = a1; fi1 = e1; fm2 = a0; fi2 = e0; }
            #pragma unroll
            for (int d = 1; d < 32; d <<= 1) {
                const float om1 = __shfl_xor_sync(FULL, fm1, d);
                const float om2 = __shfl_xor_sync(FULL, fm2, d);
                const int   oi1 = __shfl_xor_sync(FULL, fi1, d);
                const int   oi2 = __shfl_xor_sync(FULL, fi2, d);
                if (om1 > fm1) {
                    if (fm1 > om2) { fm2 = fm1; fi2 = fi1; }
                    else           { fm2 = om2; fi2 = oi2; }
                    fm1 = om1; fi1 = oi1;
                } else if (om1 > fm2) { fm2 = om1; fi2 = oi1; }
            }
            float fs = __expf(a0 - fm1) + __expf(a1 - fm1);
            #pragma unroll
            for (int d = 1; d < 32; d <<= 1)
                fs += __shfl_xor_sync(FULL, fs, d);
            em1 = fm1; ei1 = fi1; em2 = fm2; ei2 = fi2; ns = fs;
        } else {
            // candidate path: exact recompute of flagged token's top-4
            const float qm = __shfl_sync(FULL, t0, b);
            const float qs = __shfl_sync(FULL, s, b);
            int qi[4];
            qi[0] = __shfl_sync(FULL, j0, b);
            qi[1] = __shfl_sync(FULL, j1, b);
            qi[2] = __shfl_sync(FULL, j2, b);
            qi[3] = __shfl_sync(FULL, j3, b);
            float ds[4] = {0.f, 0.f, 0.f, 0.f};
            #pragma unroll
            for (int u = 0; u < 8; ++u) {
                const int k = u * 128 + lid * 4;
                const float4 xq = *(const float4*)(xr + k);
                #pragma unroll
                for (int q = 0; q < 4; ++q) {
                    const float4 wq = *(const float4*)(Wm + (size_t)qi[q] * K_DIM + k);
                    ds[q] = fmaf(xq.x, wq.x, ds[q]);
                    ds[q] = fmaf(xq.y, wq.y, ds[q]);
                    ds[q] = fmaf(xq.z, wq.z, ds[q]);
                    ds[q] = fmaf(xq.w, wq.w, ds[q]);
                }
            }
            #pragma unroll
            for (int d = 1; d < 32; d <<= 1) {
                #pragma unroll
                for (int q = 0; q < 4; ++q)
                    ds[q] += __shfl_xor_sync(FULL, ds[q], d);
            }
            #pragma unroll
            for (int q = 0; q < 4; ++q) ds[q] += __ldg(bias + qi[q]);
            em1 = ds[0]; ei1 = qi[0]; em2 = -INFINITY; ei2 = 0;
            #pragma unroll
            for (int q = 1; q < 4; ++q) {
                if (ds[q] > em1) { em2 = em1; ei2 = ei1; em1 = ds[q]; ei1 = qi[q]; }
                else if (ds[q] > em2) { em2 = ds[q]; ei2 = qi[q]; }
            }
            ns = qs * __expf(qm - em1);
        }
        if (lid == b) {
            g1 = 1.0f / ns; g2 = __expf(em2 - em1) / ns;
            i1 = ei1; i2 = ei2;
        }
    }

    {
        const int tk = bm + tid;
        float* oid = out + (size_t)num_tokens * 2;
        *(float2*)&out[tk * 2] = make_float2(g1, g2);
        *(float2*)&oid[tk * 2] = make_float2((float)i1, (float)i2);
    }
}

extern "C" void kernel_launch(void* const* d_in, const int* in_sizes, int n_in,
                              void* d_out, int out_size) {
    const float* x = (const float*)d_in[0];   // [8,4096,1024]
    const float* W = (const float*)d_in[1];   // [64,1024]
    const float* b = (const float*)d_in[2];   // [64]
    float* out = (float*)d_out;

    const int num_tokens = in_sizes[0] / K_DIM;   // 32768
    const int grid = num_tokens / BM;             // 256

    cudaFuncSetAttribute(router_mma2_kernel,
                         cudaFuncAttributeMaxDynamicSharedMemorySize, SMEM_BYTES);
    router_mma2_kernel<<<grid, 256, SMEM_BYTES>>>(x, W, b, out, num_tokens);
}